// round 8
// baseline (speedup 1.0000x reference)
#include <cuda_runtime.h>
#include <cuda_bf16.h>
#include <cstdint>

#define NPTS    16384
#define THREADS 256
#define QPT     16                      // queries per thread (8 packed f32x2 pairs)
#define QPB     (THREADS * QPT)         // 4096 queries per block
#define QC      (NPTS / QPB)            // 4 query chunks
#define TSLICES 37                      // 4 * 37 = 148 blocks = 1 per SM
#define TS_MAX  443                     // ceil(16384 / 37)
#define TS_PAD  448

// ---- device scratch (no allocations allowed) ----
__device__ float    g_minrow[TSLICES][NPTS];  // per-slice partial row mins (Xc side)
__device__ float    g_mincol[QC][NPTS];       // per-qchunk partial col mins (Xt side)
__device__ float    g_partial[128];
__device__ unsigned g_count = 0;

#define FMA2(d, a, b, c) \
    asm("fma.rn.f32x2 %0, %1, %2, %3;" : "=l"(d) : "l"(a), "l"(b), "l"(c))
#define ADD2(d, a, b) \
    asm("add.rn.f32x2 %0, %1, %2;" : "=l"(d) : "l"(a), "l"(b))
#define PACK2(d, lo, hi) \
    asm("mov.b64 %0, {%1, %2};" : "=l"(d) : "f"(lo), "f"(hi))
#define UNPK2(lo, hi, s) \
    asm("mov.b64 {%0, %1}, %2;" : "=f"(lo), "=f"(hi) : "l"(s))

// ---------------------------------------------------------------------------
// Fused single-pass: each pair (i in Xc, j in Xt) evaluated ONCE.
// d2 = a*x + b*y + c*z + (|t|^2 + |q|^2), a = -2 q.x etc.
// Row mins (Xc): per-thread register accumulators.
// Col mins (Xt): per-thread tree -> warp shuffle -> per-warp smem row.
// grid = QC * TSLICES = 148 blocks = exactly 1 CTA/SM, one wave.
// ---------------------------------------------------------------------------
__global__ __launch_bounds__(THREADS, 1) void chamfer_fused_kernel(
        const float* __restrict__ Xc, const float* __restrict__ Xt) {
    __shared__ float4 sA[TS_MAX];            // {x, x, y, y} per target
    __shared__ float4 sB[TS_MAX];            // {z, z, w, w} per target
    __shared__ float  scolw[8][TS_PAD];      // per-warp col mins

    const int bid = blockIdx.x;
    const int qc  = bid / TSLICES;           // 0..3
    const int ts  = bid % TSLICES;           // 0..36
    const int qbase = qc * QPB;
    const int t0  = ts * TS_MAX;
    const int nt  = min(TS_MAX, NPTS - t0);
    const int tid = threadIdx.x;
    const int wid = tid >> 5;
    const int lane = tid & 31;

    // ---- stage this slice's targets, computing |t|^2 on the fly ----
    for (int idx = tid; idx < nt; idx += THREADS) {
        float x = Xt[3 * (t0 + idx) + 0];
        float y = Xt[3 * (t0 + idx) + 1];
        float z = Xt[3 * (t0 + idx) + 2];
        float w = fmaf(x, x, fmaf(y, y, z * z));
        sA[idx] = make_float4(x, x, y, y);
        sB[idx] = make_float4(z, z, w, w);
    }

    // ---- load 16 queries per thread, build packed coefficients ----
    unsigned long long aa[8], bb[8], cc[8], ww[8];
    #pragma unroll
    for (int p = 0; p < 8; p++) {
        int qe = qbase + (2 * p) * THREADS + tid;
        int qo = qe + THREADS;
        float xe = Xc[3 * qe], ye = Xc[3 * qe + 1], ze = Xc[3 * qe + 2];
        float xo = Xc[3 * qo], yo = Xc[3 * qo + 1], zo = Xc[3 * qo + 2];
        PACK2(aa[p], -2.0f * xe, -2.0f * xo);
        PACK2(bb[p], -2.0f * ye, -2.0f * yo);
        PACK2(cc[p], -2.0f * ze, -2.0f * zo);
        PACK2(ww[p], fmaf(xe, xe, fmaf(ye, ye, ze * ze)),
                     fmaf(xo, xo, fmaf(yo, yo, zo * zo)));
    }

    float mn[16];
    #pragma unroll
    for (int q = 0; q < 16; q++) mn[q] = 3.4e38f;

    __syncthreads();

    // ---- main loop: one pass over targets ----
    #pragma unroll 2
    for (int j = 0; j < nt; j++) {
        const ulonglong2 A = *reinterpret_cast<const ulonglong2*>(&sA[j]);
        const ulonglong2 B = *reinterpret_cast<const ulonglong2*>(&sB[j]);
        float d[16];
        #pragma unroll
        for (int p = 0; p < 8; p++) {
            unsigned long long t, v;
            ADD2(t, B.y, ww[p]);            // |t|^2 + |q|^2  (packed)
            FMA2(v, cc[p], B.x, t);         // + c*z
            FMA2(v, bb[p], A.y, v);         // + b*y
            FMA2(v, aa[p], A.x, v);         // + a*x   -> full d^2
            UNPK2(d[2 * p], d[2 * p + 1], v);
            mn[2 * p]     = fminf(mn[2 * p],     d[2 * p]);
            mn[2 * p + 1] = fminf(mn[2 * p + 1], d[2 * p + 1]);
        }
        // col min for target j: tree over this thread's 16 queries
        float c01 = fminf(fminf(fminf(d[0], d[1]),  fminf(d[2], d[3])),
                          fminf(fminf(d[4], d[5]),  fminf(d[6], d[7])));
        float c23 = fminf(fminf(fminf(d[8], d[9]),  fminf(d[10], d[11])),
                          fminf(fminf(d[12], d[13]), fminf(d[14], d[15])));
        float c = fminf(c01, c23);
        // warp reduce
        #pragma unroll
        for (int off = 16; off > 0; off >>= 1)
            c = fminf(c, __shfl_xor_sync(0xFFFFFFFFu, c, off));
        if (lane == 0) scolw[wid][j] = c;
    }

    // ---- row outputs: partial mins over this slice ----
    #pragma unroll
    for (int q = 0; q < 16; q++)
        g_minrow[ts][qbase + q * THREADS + tid] = mn[q];

    __syncthreads();

    // ---- col outputs: combine the 8 warp rows ----
    for (int j = tid; j < nt; j += THREADS) {
        float m = fminf(fminf(fminf(scolw[0][j], scolw[1][j]),
                              fminf(scolw[2][j], scolw[3][j])),
                        fminf(fminf(scolw[4][j], scolw[5][j]),
                              fminf(scolw[6][j], scolw[7][j])));
        g_mincol[qc][t0 + j] = m;
    }
}

// ---------------------------------------------------------------------------
// Combine partial mins, clamp, reduce, and finish in the last-done block.
// grid = 128 blocks * 256 threads = 32768 entries.
// Blocks 0-63: Xc rows; blocks 64-127: Xt cols (uniform per block).
// ---------------------------------------------------------------------------
__global__ void chamfer_combine_kernel(float* __restrict__ out) {
    __shared__ float red[8];
    int idx = blockIdx.x * 256 + threadIdx.x;     // 0..32767

    float m;
    if (idx < NPTS) {
        m = 3.4e38f;
        #pragma unroll
        for (int s = 0; s < TSLICES; s++)
            m = fminf(m, g_minrow[s][idx]);
    } else {
        int j = idx - NPTS;
        m = fminf(fminf(g_mincol[0][j], g_mincol[1][j]),
                  fminf(g_mincol[2][j], g_mincol[3][j]));
    }
    float r = fmaxf(m, 0.0f);     // matches reference maximum(d2, 0) before min

    #pragma unroll
    for (int off = 16; off > 0; off >>= 1)
        r += __shfl_xor_sync(0xFFFFFFFFu, r, off);

    int lane = threadIdx.x & 31, warp = threadIdx.x >> 5;
    if (lane == 0) red[warp] = r;
    __syncthreads();
    if (threadIdx.x == 0) {
        float s = red[0];
        #pragma unroll
        for (int w = 1; w < 8; w++) s += red[w];
        g_partial[blockIdx.x] = s;
        __threadfence();
        unsigned done = atomicAdd(&g_count, 1u);
        if (done == 127u) {
            // deterministic fixed-order final sum
            float tot = 0.0f;
            #pragma unroll
            for (int b = 0; b < 128; b++) tot += g_partial[b];
            out[0] = tot * (1.0f / (float)NPTS);
            g_count = 0;    // reset for next graph replay
        }
    }
}

// ---------------------------------------------------------------------------
extern "C" void kernel_launch(void* const* d_in, const int* in_sizes, int n_in,
                              void* d_out, int out_size) {
    const float* xc = (const float*)d_in[0];
    const float* xt = (const float*)d_in[1];
    float* out = (float*)d_out;

    chamfer_fused_kernel<<<QC * TSLICES, THREADS>>>(xc, xt);
    chamfer_combine_kernel<<<128, 256>>>(out);
}

// round 10
// speedup vs baseline: 1.3916x; 1.3916x over previous
#include <cuda_runtime.h>
#include <cuda_bf16.h>
#include <cstdint>

#define NPTS    16384
#define THREADS 256
#define QPT     16                      // queries per thread (8 packed f32x2 pairs)
#define QPB     (THREADS * QPT)         // 4096 queries per block
#define QC      (NPTS / QPB)            // 4 query chunks
#define TSLICES 37                      // 4 * 37 = 148 blocks = 1 per SM
#define TS_MAX  443                     // real targets per slice (last: 436)
#define TS_PAD  448                     // padded to 14 groups of 32

// ---- device scratch (no allocations allowed) ----
__device__ float    g_minrow[TSLICES][NPTS];  // per-slice partial row mins (Xc side)
__device__ float    g_mincol[QC][NPTS];       // per-qchunk partial col mins (Xt side)
__device__ float    g_partial[128];
__device__ unsigned g_count = 0;

#define FMA2(d, a, b, c) \
    asm("fma.rn.f32x2 %0, %1, %2, %3;" : "=l"(d) : "l"(a), "l"(b), "l"(c))
#define ADD2(d, a, b) \
    asm("add.rn.f32x2 %0, %1, %2;" : "=l"(d) : "l"(a), "l"(b))
#define PACK2(d, lo, hi) \
    asm("mov.b64 %0, {%1, %2};" : "=l"(d) : "f"(lo), "f"(hi))
#define UNPK2(lo, hi, s) \
    asm("mov.b64 {%0, %1}, %2;" : "=f"(lo), "=f"(hi) : "l"(s))

// ---------------------------------------------------------------------------
// Fused single-pass, rotation scheme. Each (i,j) pair evaluated once.
// Row mins: per-thread registers (each lane sees every target via rotation).
// Col mins: per-warp smem accumulators, plain LDS/FMNMX/STS — no shuffles.
// grid = QC * TSLICES = 148 blocks = 1 CTA/SM, one wave.
// ---------------------------------------------------------------------------
__global__ __launch_bounds__(THREADS, 1) void chamfer_fused_kernel(
        const float* __restrict__ Xc, const float* __restrict__ Xt) {
    __shared__ float4 sA[TS_PAD];            // {x, x, y, y} per target
    __shared__ float4 sB[TS_PAD];            // {z, z, w, w} per target (w=|t|^2)
    __shared__ float  scolw[8][TS_PAD];      // per-warp col-min accumulators

    const int bid = blockIdx.x;
    const int qc  = bid / TSLICES;           // 0..3
    const int ts  = bid % TSLICES;           // 0..36
    const int qbase = qc * QPB;
    const int t0  = ts * TS_MAX;
    const int nt  = min(TS_MAX, NPTS - t0);
    const int tid = threadIdx.x;
    const int wid = tid >> 5;
    const int lane = tid & 31;

    // ---- stage targets (sentinel-pad to 448) + init col accumulators ----
    #pragma unroll
    for (int k = 0; k < 2; k++) {
        int idx = tid + k * THREADS;
        if (idx < TS_PAD) {
            float x = 0.0f, y = 0.0f, z = 0.0f, w = 1e30f;
            if (idx < nt) {
                int gi = t0 + idx;
                x = Xt[3 * gi + 0]; y = Xt[3 * gi + 1]; z = Xt[3 * gi + 2];
                w = fmaf(x, x, fmaf(y, y, z * z));
            }
            sA[idx] = make_float4(x, x, y, y);
            sB[idx] = make_float4(z, z, w, w);
        }
    }
    #pragma unroll
    for (int k = 0; k < (8 * TS_PAD) / THREADS; k++)
        (&scolw[0][0])[tid + k * THREADS] = 3.4e38f;

    // ---- 16 queries per thread -> 8 packed coefficient quads ----
    unsigned long long aa[8], bb[8], cc[8], ww[8];
    #pragma unroll
    for (int p = 0; p < 8; p++) {
        int qe = qbase + (2 * p) * THREADS + tid;
        int qo = qe + THREADS;
        float xe = Xc[3 * qe], ye = Xc[3 * qe + 1], ze = Xc[3 * qe + 2];
        float xo = Xc[3 * qo], yo = Xc[3 * qo + 1], zo = Xc[3 * qo + 2];
        PACK2(aa[p], -2.0f * xe, -2.0f * xo);
        PACK2(bb[p], -2.0f * ye, -2.0f * yo);
        PACK2(cc[p], -2.0f * ze, -2.0f * zo);
        PACK2(ww[p], fmaf(xe, xe, fmaf(ye, ye, ze * ze)),
                     fmaf(xo, xo, fmaf(yo, yo, zo * zo)));
    }

    float mn[16];
    #pragma unroll
    for (int q = 0; q < 16; q++) mn[q] = 3.4e38f;

    __syncthreads();

    // ---- main loop: 14 groups of 32 targets, rotated across lanes ----
    for (int g = 0; g < TS_PAD; g += 32) {
        int idx = g + lane;
        #pragma unroll 4
        for (int t = 0; t < 32; t++) {
            const ulonglong2 A = *reinterpret_cast<const ulonglong2*>(&sA[idx]);
            const ulonglong2 B = *reinterpret_cast<const ulonglong2*>(&sB[idx]);
            float d[16];
            #pragma unroll
            for (int p = 0; p < 8; p++) {
                unsigned long long s, v;
                ADD2(s, B.y, ww[p]);        // |t|^2 + |q|^2 (packed)
                FMA2(v, cc[p], B.x, s);     // + c*z
                FMA2(v, bb[p], A.y, v);     // + b*y
                FMA2(v, aa[p], A.x, v);     // + a*x  -> full d^2 (x2)
                UNPK2(d[2 * p], d[2 * p + 1], v);
                mn[2 * p]     = fminf(mn[2 * p],     d[2 * p]);
                mn[2 * p + 1] = fminf(mn[2 * p + 1], d[2 * p + 1]);
            }
            // col contribution: tree over this thread's 16 queries
            float c = fminf(
                fminf(fminf(fminf(d[0], d[1]),   fminf(d[2], d[3])),
                      fminf(fminf(d[4], d[5]),   fminf(d[6], d[7]))),
                fminf(fminf(fminf(d[8], d[9]),   fminf(d[10], d[11])),
                      fminf(fminf(d[12], d[13]), fminf(d[14], d[15]))));
            scolw[wid][idx] = fminf(scolw[wid][idx], c);
            idx = (idx == g + 31) ? g : idx + 1;    // rotate within group
        }
    }

    // ---- row outputs: partial mins over this slice ----
    float* __restrict__ outr = g_minrow[ts];
    #pragma unroll
    for (int q = 0; q < 16; q++)
        outr[qbase + q * THREADS + tid] = mn[q];

    __syncthreads();

    // ---- col outputs: merge the 8 warp rows ----
    for (int j = tid; j < nt; j += THREADS) {
        float m = fminf(fminf(fminf(scolw[0][j], scolw[1][j]),
                              fminf(scolw[2][j], scolw[3][j])),
                        fminf(fminf(scolw[4][j], scolw[5][j]),
                              fminf(scolw[6][j], scolw[7][j])));
        g_mincol[qc][t0 + j] = m;
    }
}

// ---------------------------------------------------------------------------
// Combine partials, clamp, reduce; last-done block finishes deterministically.
// ---------------------------------------------------------------------------
__global__ void chamfer_combine_kernel(float* __restrict__ out) {
    __shared__ float red[8];
    int idx = blockIdx.x * 256 + threadIdx.x;     // 0..32767

    float m;
    if (idx < NPTS) {
        m = 3.4e38f;
        #pragma unroll
        for (int s = 0; s < TSLICES; s++)
            m = fminf(m, g_minrow[s][idx]);
    } else {
        int j = idx - NPTS;
        m = fminf(fminf(g_mincol[0][j], g_mincol[1][j]),
                  fminf(g_mincol[2][j], g_mincol[3][j]));
    }
    float r = fmaxf(m, 0.0f);     // matches reference maximum(d2, 0)

    #pragma unroll
    for (int off = 16; off > 0; off >>= 1)
        r += __shfl_xor_sync(0xFFFFFFFFu, r, off);

    int lane = threadIdx.x & 31, warp = threadIdx.x >> 5;
    if (lane == 0) red[warp] = r;
    __syncthreads();
    if (threadIdx.x == 0) {
        float s = red[0];
        #pragma unroll
        for (int w = 1; w < 8; w++) s += red[w];
        g_partial[blockIdx.x] = s;
        __threadfence();
        unsigned done = atomicAdd(&g_count, 1u);
        if (done == 127u) {
            float tot = 0.0f;
            #pragma unroll
            for (int b = 0; b < 128; b++) tot += g_partial[b];
            out[0] = tot * (1.0f / (float)NPTS);
            g_count = 0;    // reset for next graph replay
        }
    }
}

// ---------------------------------------------------------------------------
extern "C" void kernel_launch(void* const* d_in, const int* in_sizes, int n_in,
                              void* d_out, int out_size) {
    const float* xc = (const float*)d_in[0];
    const float* xt = (const float*)d_in[1];
    float* out = (float*)d_out;

    chamfer_fused_kernel<<<QC * TSLICES, THREADS>>>(xc, xt);
    chamfer_combine_kernel<<<128, 256>>>(out);
}